// round 4
// baseline (speedup 1.0000x reference)
#include <cuda_runtime.h>

#define BB 16
#define NN 1024
#define DD 1024   // D2H
#define UU 512
#define TOK (BB * NN)
#define UCHUNKS 8
#define UC (UU / UCHUNKS)          // 64
#define ROW_BLOCKS (TOK / 8)       // 2048 (8 rows per block, warp per row)
#define OUT_BLOCKS (TOK / 8)       // 2048 (8 rows per block)
#define RB_PER_BATCH (NN / 8)      // 128 row-blocks per batch

// Scratch (no device allocation allowed; rewritten every launch).
__device__ float g_ph[UCHUNKS * DD];
__device__ float g_pm[UCHUNKS * DD];
__device__ float g_vh[DD];
__device__ float g_vm[DD];
__device__ float g_const;
__device__ float g_sH[TOK];
__device__ float g_sM[TOK];
__device__ int   g_done[BB];

// ---------------------------------------------------------------------------
// Stage 0: zero the per-batch completion counters (graph replays reuse them).
// ---------------------------------------------------------------------------
__global__ void k_zero() {
    if (threadIdx.x < BB) g_done[threadIdx.x] = 0;
}

// ---------------------------------------------------------------------------
// Stage 1: partial v_h/v_m.  v_h[d] = sum_u W_h[u,d] * w_out[u]
// ---------------------------------------------------------------------------
__global__ void k_vec_partial(const float* __restrict__ Wh,
                              const float* __restrict__ Wm,
                              const float* __restrict__ wout) {
    int d  = blockIdx.x * 128 + threadIdx.x;
    int u0 = blockIdx.y * UC;
    float ah = 0.f, am = 0.f;
#pragma unroll 16
    for (int i = 0; i < UC; ++i) {
        float w = __ldg(&wout[u0 + i]);
        ah = fmaf(Wh[(size_t)(u0 + i) * DD + d], w, ah);
        am = fmaf(Wm[(size_t)(u0 + i) * DD + d], w, am);
    }
    g_ph[blockIdx.y * DD + d] = ah;
    g_pm[blockIdx.y * DD + d] = am;
}

// ---------------------------------------------------------------------------
// Stage 2 (fused): blocks 0..3 fold partials into v_h/v_m; block 4 computes
// g_const = (b_h + b_m) . w_out + b_out.
// ---------------------------------------------------------------------------
__global__ void k_finish(const float* __restrict__ bh,
                         const float* __restrict__ bm,
                         const float* __restrict__ wout,
                         const float* __restrict__ bout) {
    int t = threadIdx.x;
    if (blockIdx.x < 4) {
        int d = blockIdx.x * 256 + t;
        float ah = 0.f, am = 0.f;
#pragma unroll
        for (int c = 0; c < UCHUNKS; ++c) {
            ah += g_ph[c * DD + d];
            am += g_pm[c * DD + d];
        }
        g_vh[d] = ah;
        g_vm[d] = am;
    } else {
        __shared__ float red[8];
        float acc = (bh[t] + bm[t]) * wout[t]
                  + (bh[t + 256] + bm[t + 256]) * wout[t + 256];
#pragma unroll
        for (int o = 16; o > 0; o >>= 1)
            acc += __shfl_down_sync(0xffffffffu, acc, o);
        if ((t & 31) == 0) red[t >> 5] = acc;
        __syncthreads();
        if (t < 8) {
            acc = red[t];
#pragma unroll
            for (int o = 4; o > 0; o >>= 1)
                acc += __shfl_down_sync(0x000000ffu, acc, o);
            if (t == 0) g_const = acc + bout[0];
        }
    }
}

// ---------------------------------------------------------------------------
// Stage 3 (fused row+out pipeline).
//   bids [0, ROW_BLOCKS): warp-per-row dual dot.  ALL 8 x-loads are issued
//     into a register array BEFORE any consumer of them (true MLP=8);
//     __launch_bounds__(256,4) grants 64 regs so ptxas can hold them.
//   bids [ROW_BLOCKS, ...): wait for own batch, write 8 output rows.
// ---------------------------------------------------------------------------
__global__ void __launch_bounds__(256, 4)
k_main(const float* __restrict__ x, float* __restrict__ out) {
    int bid = blockIdx.x;
    int t   = threadIdx.x;

    if (bid < ROW_BLOCKS) {
        // ---- producer: dual dot products for 8 rows, warp per row ----
        int row  = bid * 8 + (t >> 5);
        int lane = t & 31;
        const float4* xr  = reinterpret_cast<const float4*>(x + (size_t)row * DD);
        const float4* vh4 = reinterpret_cast<const float4*>(g_vh);
        const float4* vm4 = reinterpret_cast<const float4*>(g_vm);

        float4 xv[8];
#pragma unroll
        for (int i = 0; i < 8; ++i)
            xv[i] = __ldcs(&xr[lane + 32 * i]);     // 8 independent LDG.128

        float ah = 0.f, am = 0.f;
#pragma unroll
        for (int i = 0; i < 8; ++i) {
            int idx = lane + 32 * i;
            float4 h = vh4[idx];
            float4 m = vm4[idx];
            ah = fmaf(xv[i].x, h.x, fmaf(xv[i].y, h.y, fmaf(xv[i].z, h.z, fmaf(xv[i].w, h.w, ah))));
            am = fmaf(xv[i].x, m.x, fmaf(xv[i].y, m.y, fmaf(xv[i].z, m.z, fmaf(xv[i].w, m.w, am))));
        }
#pragma unroll
        for (int o = 16; o > 0; o >>= 1) {
            ah += __shfl_xor_sync(0xffffffffu, ah, o);
            am += __shfl_xor_sync(0xffffffffu, am, o);
        }
        if (lane == 0) {
            g_sH[row] = ah;
            g_sM[row] = am;
            __threadfence();                        // release own stores
        }
        __syncthreads();
        if (t == 0) atomicAdd(&g_done[bid >> 7], 1);   // RB_PER_BATCH = 128
    } else {
        // ---- consumer: write 8 output rows of one batch ----
        int ob = bid - ROW_BLOCKS;
        int i0 = ob * 8;            // global row base (b*NN + i)
        int b  = i0 >> 10;          // NN = 1024

        if (t == 0) {
            while (*(volatile int*)&g_done[b] < RB_PER_BATCH)
                __nanosleep(128);
            __threadfence();        // acquire
        }
        __syncthreads();

        float4 m = reinterpret_cast<const float4*>(g_sM + (size_t)b * NN)[t];
        float  c = g_const;
        float4 h0 = reinterpret_cast<const float4*>(g_sH + i0)[0];
        float4 h1 = reinterpret_cast<const float4*>(g_sH + i0)[1];
        float base[8] = {h0.x + c, h0.y + c, h0.z + c, h0.w + c,
                         h1.x + c, h1.y + c, h1.z + c, h1.w + c};
#pragma unroll
        for (int r = 0; r < 8; ++r) {
            __stcs(reinterpret_cast<float4*>(out + (size_t)(i0 + r) * NN) + t,
                   make_float4(base[r] + m.x, base[r] + m.y,
                               base[r] + m.z, base[r] + m.w));
        }
    }
}

extern "C" void kernel_launch(void* const* d_in, const int* in_sizes, int n_in,
                              void* d_out, int out_size) {
    const float* x    = (const float*)d_in[0];
    const float* Wh   = (const float*)d_in[1];
    const float* bh   = (const float*)d_in[2];
    const float* Wm   = (const float*)d_in[3];
    const float* bm   = (const float*)d_in[4];
    const float* wout = (const float*)d_in[5];
    const float* bout = (const float*)d_in[6];
    float* out = (float*)d_out;

    k_zero<<<1, 32>>>();
    k_vec_partial<<<dim3(DD / 128, UCHUNKS), 128>>>(Wh, Wm, wout);
    k_finish<<<5, 256>>>(bh, bm, wout, bout);
    k_main<<<ROW_BLOCKS + OUT_BLOCKS, 256>>>(x, out);
}